// round 11
// baseline (speedup 1.0000x reference)
#include <cuda_runtime.h>
#include <math.h>

// Fixed problem: B=128, T=514, D=8, H=64, L=2, IN=17, W=512, N=65536
// out layout: [0,524288) residuals (B,W,D) | [524288,524416) logdet (B,)
//             [524416,8913024) hist_jac (D,N,16)
#define SLOPE 0.2f
#define SACT 132          // activation row stride (128 samples + pad)
#define SW   68           // weight row stride (64 + pad)

// smem float offsets
#define OFF_OUT 0          // [8][128] partial head sums (reuses X region)
#define OFF_J   1024       // [64] logdet partials      (reuses X region)
#define OFF_X   0          // [17][SACT] layer-0 inputs (freed after layer 0)
#define OFF_A   2244       // [64][SACT] ping
#define OFF_B   10692      // [64][SACT] pong
#define OFF_WA  19140      // [64][SW] weight buffer A
#define OFF_WB  23492      // [64][SW] weight buffer B
#define OFF_SB0 27844
#define OFF_SB1 27908
#define OFF_SB2 27972
#define OFF_SWO 28036
#define OFF_FLAG 28100     // last-block flag
#define SMEM_FLOATS 28104
#define SMEM_BYTES  (SMEM_FLOATS * 4)

typedef unsigned long long u64;
typedef unsigned int u32;

__device__ float g_partials[4096];   // [d][tile] (8 x 512)
__device__ u32   g_done = 0;         // finished-block counter (reset by last block)

__device__ __forceinline__ u64 ffma2(u64 a, u64 b, u64 c) {
    u64 d; asm("fma.rn.f32x2 %0, %1, %2, %3;" : "=l"(d) : "l"(a), "l"(b), "l"(c)); return d;
}
__device__ __forceinline__ u64 pack2(float x, float y) {
    u64 r; asm("mov.b64 %0, {%1, %2};" : "=l"(r) : "f"(x), "f"(y)); return r;
}
__device__ __forceinline__ float2 unpk(u64 v) {
    float2 r; asm("mov.b64 {%0, %1}, %2;" : "=f"(r.x), "=f"(r.y) : "l"(v)); return r;
}
__device__ __forceinline__ float lk(float v) { return v > 0.f ? v : v * SLOPE; }
__device__ __forceinline__ float mb(u32 m, int b) { return ((m >> b) & 1u) ? 1.f : SLOPE; }

// Weight column permutation (interleave so each lane's 8 outs are two 16B
// chunks that make the WARP's loads line-contiguous):
//   perm(c) = (c&4)*8 + (c>>3)*4 + (c&3)
__device__ __forceinline__ int wperm(int c) {
    return ((c & 4) << 3) + ((c >> 3) << 2) + (c & 3);
}

// 8 outputs (4 packed pairs, outs so*8..+7) x 4 samples (sb..+3) per thread.
// acc[p*4+j]: pair p, sample j. Weights in interleaved layout; acts row-rotated:
//   act col of (row k, sample chunk sb) = (sb + (k>>3)*4) & 127.
// Per k per warp: ~1 act wf + 2 weight wf.
__device__ __forceinline__ void gemm8x4(const float* __restrict__ A,
                                        const float* __restrict__ wp,  // Wc + so*4
                                        int K, int sb, u64* acc) {
#pragma unroll 4
    for (int k = 0; k < K; ++k) {
        float4 a = *(const float4*)(A + k * SACT + ((sb + ((k >> 3) << 2)) & 127));
        ulonglong2 w01 = *(const ulonglong2*)(wp + k * SW);        // outs so*8..+3
        ulonglong2 w23 = *(const ulonglong2*)(wp + k * SW + 32);   // outs so*8+4..+7
        u64 a0 = pack2(a.x, a.x), a1 = pack2(a.y, a.y);
        u64 a2 = pack2(a.z, a.z), a3 = pack2(a.w, a.w);
        acc[0]  = ffma2(w01.x, a0, acc[0]);   acc[1]  = ffma2(w01.x, a1, acc[1]);
        acc[2]  = ffma2(w01.x, a2, acc[2]);   acc[3]  = ffma2(w01.x, a3, acc[3]);
        acc[4]  = ffma2(w01.y, a0, acc[4]);   acc[5]  = ffma2(w01.y, a1, acc[5]);
        acc[6]  = ffma2(w01.y, a2, acc[6]);   acc[7]  = ffma2(w01.y, a3, acc[7]);
        acc[8]  = ffma2(w23.x, a0, acc[8]);   acc[9]  = ffma2(w23.x, a1, acc[9]);
        acc[10] = ffma2(w23.x, a2, acc[10]);  acc[11] = ffma2(w23.x, a3, acc[11]);
        acc[12] = ffma2(w23.y, a0, acc[12]);  acc[13] = ffma2(w23.y, a1, acc[13]);
        acc[14] = ffma2(w23.y, a2, acc[14]);  acc[15] = ffma2(w23.y, a3, acc[15]);
    }
}

// Coalesced row-major prefetch: thread gets W[h][4c..4c+3], h=i4>>4, c4=(i4&15)*4.
#define PREF_R(SRC)                                                        \
    _Pragma("unroll")                                                      \
    for (int q = 0; q < 4; ++q) pre[q] = ((const float4*)(SRC))[q * 256 + tid];
// Store [contraction=h][perm(cols)] for backward gemms (4-aligned chunk stays float4).
#define STS_RP(DST)                                                        \
    _Pragma("unroll")                                                      \
    for (int q = 0; q < 4; ++q) {                                          \
        int i4 = q * 256 + tid;                                            \
        int P = ((i4 & 1) << 5) + (((i4 >> 1) & 7) << 2);                  \
        *(float4*)(sm + (DST) + (i4 >> 4) * SW + P) = pre[q];              \
    }
// Store transposed [k][perm(h)] for forward gemms.
#define STS_TRP(DST)                                                       \
    _Pragma("unroll")                                                      \
    for (int q = 0; q < 4; ++q) {                                          \
        int i4 = q * 256 + tid;                                            \
        int h = i4 >> 4, c4 = (i4 & 15) * 4;                               \
        float* dp = sm + (DST) + wperm(h);                                 \
        dp[(c4 + 0) * SW] = pre[q].x;                                      \
        dp[(c4 + 1) * SW] = pre[q].y;                                      \
        dp[(c4 + 2) * SW] = pre[q].z;                                      \
        dp[(c4 + 3) * SW] = pre[q].w;                                      \
    }

// Forward-activation epilogue for pair p: rows so*8+2p (lo), +1 (hi),
// 4 samples at rotated column ecol.
#define STORE_ACT(BUF, P, V0, V1, V2, V3, F)                                         \
    do {                                                                             \
        *(float4*)(sm + (BUF) + (so * 8 + 2 * (P)) * SACT + ecol) =                  \
            make_float4(F(V0.x), F(V1.x), F(V2.x), F(V3.x));                         \
        *(float4*)(sm + (BUF) + (so * 8 + 2 * (P) + 1) * SACT + ecol) =              \
            make_float4(F(V0.y), F(V1.y), F(V2.y), F(V3.y));                         \
    } while (0)

__global__ void __launch_bounds__(256, 2)
mlp_tile_kernel(const float* __restrict__ x,
                const float* __restrict__ W0, const float* __restrict__ b0,
                const float* __restrict__ W1, const float* __restrict__ b1,
                const float* __restrict__ W2, const float* __restrict__ b2,
                const float* __restrict__ Wo, const float* __restrict__ bo,
                float* __restrict__ out)
{
    extern __shared__ float sm[];
    const int tid  = threadIdx.x;
    const int lane = tid & 31;
    const int warp = tid >> 5;      // 8 warps
    const int sx   = lane & 3;      // sample subgroup
    const int so   = lane >> 2;     // out group (outs so*8 .. +7)
    const int sb   = warp * 16 + sx * 4;        // raw sample base (0..124)
    const int ecol = (sb + so * 4) & 127;       // rotated store column (rows>>3 == so)
    const int tile = blockIdx.x;    // 0..511 (128 samples)
    const int d    = blockIdx.y;

    const float bo_d = bo[d];

    // -------- phase 1: stage X (rotated), W0^T (perm) -> WA, biases --------
    {
        const int s = tid & 127, half = tid >> 7;
        const int n = tile * 128 + s;
        const float* xb = x + (size_t)((n >> 9) * 514 + (n & 511)) * 8;
        float4 v0 = *(const float4*)(xb + half * 8);
        float4 v1 = *(const float4*)(xb + half * 8 + 4);
        // rows half*8 .. half*8+7  -> rot = half*4 ; row 16 -> rot 8
        const int c = (s + half * 4) & 127;
        float* dst = sm + OFF_X + c;
        dst[(half * 8 + 0) * SACT] = v0.x;  dst[(half * 8 + 1) * SACT] = v0.y;
        dst[(half * 8 + 2) * SACT] = v0.z;  dst[(half * 8 + 3) * SACT] = v0.w;
        dst[(half * 8 + 4) * SACT] = v1.x;  dst[(half * 8 + 5) * SACT] = v1.y;
        dst[(half * 8 + 6) * SACT] = v1.z;  dst[(half * 8 + 7) * SACT] = v1.w;
        if (half == 0) sm[OFF_X + 16 * SACT + ((s + 8) & 127)] = xb[16 + d];
    }
    for (int i = tid; i < 1088; i += 256) {         // W0^T [k][perm(h)]
        int h = i / 17, k = i - 17 * h;
        sm[OFF_WA + k * SW + wperm(h)] = W0[d * 1088 + i];
    }
    if (tid < 64) {
        sm[OFF_SB0 + tid] = b0[d * 64 + tid];
        sm[OFF_SB1 + tid] = b1[d * 64 + tid];
        sm[OFF_SB2 + tid] = b2[d * 64 + tid];
        sm[OFF_SWO + tid] = Wo[d * 64 + tid];
    }
    __syncthreads();

    u64 acc[16];
    u32 m0 = 0, m1 = 0;
    float4 pre[4];

    // -------- phase 2: L0 (X, WA) -> A; prefetch W1 -> WB^T(perm) --------
    PREF_R(W1 + d * 4096);
#pragma unroll
    for (int p = 0; p < 4; ++p) {
        u64 bp = *(const u64*)(sm + OFF_SB0 + so * 8 + 2 * p);
        acc[p * 4 + 0] = bp; acc[p * 4 + 1] = bp; acc[p * 4 + 2] = bp; acc[p * 4 + 3] = bp;
    }
    gemm8x4(sm + OFF_X, sm + OFF_WA + so * 4, 17, sb, acc);
#pragma unroll
    for (int p = 0; p < 4; ++p) {
        float2 v0 = unpk(acc[p * 4 + 0]), v1 = unpk(acc[p * 4 + 1]);
        float2 v2 = unpk(acc[p * 4 + 2]), v3 = unpk(acc[p * 4 + 3]);
        m0 |= ((u32)(v0.x > 0.f) << (p * 8 + 0)) | ((u32)(v0.y > 0.f) << (p * 8 + 1))
            | ((u32)(v1.x > 0.f) << (p * 8 + 2)) | ((u32)(v1.y > 0.f) << (p * 8 + 3))
            | ((u32)(v2.x > 0.f) << (p * 8 + 4)) | ((u32)(v2.y > 0.f) << (p * 8 + 5))
            | ((u32)(v3.x > 0.f) << (p * 8 + 6)) | ((u32)(v3.y > 0.f) << (p * 8 + 7));
        STORE_ACT(OFF_A, p, v0, v1, v2, v3, lk);
    }
    STS_TRP(OFF_WB);
    __syncthreads();

    // -------- phase 3: L1 (A, WB) -> B; prefetch W2 -> WA^T(perm) --------
    PREF_R(W2 + d * 4096);
#pragma unroll
    for (int p = 0; p < 4; ++p) {
        u64 bp = *(const u64*)(sm + OFF_SB1 + so * 8 + 2 * p);
        acc[p * 4 + 0] = bp; acc[p * 4 + 1] = bp; acc[p * 4 + 2] = bp; acc[p * 4 + 3] = bp;
    }
    gemm8x4(sm + OFF_A, sm + OFF_WB + so * 4, 64, sb, acc);
#pragma unroll
    for (int p = 0; p < 4; ++p) {
        float2 v0 = unpk(acc[p * 4 + 0]), v1 = unpk(acc[p * 4 + 1]);
        float2 v2 = unpk(acc[p * 4 + 2]), v3 = unpk(acc[p * 4 + 3]);
        m1 |= ((u32)(v0.x > 0.f) << (p * 8 + 0)) | ((u32)(v0.y > 0.f) << (p * 8 + 1))
            | ((u32)(v1.x > 0.f) << (p * 8 + 2)) | ((u32)(v1.y > 0.f) << (p * 8 + 3))
            | ((u32)(v2.x > 0.f) << (p * 8 + 4)) | ((u32)(v2.y > 0.f) << (p * 8 + 5))
            | ((u32)(v3.x > 0.f) << (p * 8 + 6)) | ((u32)(v3.y > 0.f) << (p * 8 + 7));
        STORE_ACT(OFF_B, p, v0, v1, v2, v3, lk);
    }
    STS_TRP(OFF_WA);
    __syncthreads();

    // -------- phase 4: L2 + head (B, WA) -> g in A; prefetch W2 -> WB (perm rows) --------
    PREF_R(W2 + d * 4096);
#pragma unroll
    for (int p = 0; p < 4; ++p) {
        u64 bp = *(const u64*)(sm + OFF_SB2 + so * 8 + 2 * p);
        acc[p * 4 + 0] = bp; acc[p * 4 + 1] = bp; acc[p * 4 + 2] = bp; acc[p * 4 + 3] = bp;
    }
    gemm8x4(sm + OFF_B, sm + OFF_WA + so * 4, 64, sb, acc);
    {
        float4 osum = make_float4(0.f, 0.f, 0.f, 0.f);
#pragma unroll
        for (int p = 0; p < 4; ++p) {
            float wl = sm[OFF_SWO + so * 8 + 2 * p];
            float wh = sm[OFF_SWO + so * 8 + 2 * p + 1];
            float2 v0 = unpk(acc[p * 4 + 0]), v1 = unpk(acc[p * 4 + 1]);
            float2 v2 = unpk(acc[p * 4 + 2]), v3 = unpk(acc[p * 4 + 3]);
            float gl0 = wl * (v0.x > 0.f ? 1.f : SLOPE), gh0 = wh * (v0.y > 0.f ? 1.f : SLOPE);
            float gl1 = wl * (v1.x > 0.f ? 1.f : SLOPE), gh1 = wh * (v1.y > 0.f ? 1.f : SLOPE);
            float gl2 = wl * (v2.x > 0.f ? 1.f : SLOPE), gh2 = wh * (v2.y > 0.f ? 1.f : SLOPE);
            float gl3 = wl * (v3.x > 0.f ? 1.f : SLOPE), gh3 = wh * (v3.y > 0.f ? 1.f : SLOPE);
            osum.x = fmaf(gl0, v0.x, fmaf(gh0, v0.y, osum.x));
            osum.y = fmaf(gl1, v1.x, fmaf(gh1, v1.y, osum.y));
            osum.z = fmaf(gl2, v2.x, fmaf(gh2, v2.y, osum.z));
            osum.w = fmaf(gl3, v3.x, fmaf(gh3, v3.y, osum.w));
            *(float4*)(sm + OFF_A + (so * 8 + 2 * p) * SACT + ecol) =
                make_float4(gl0, gl1, gl2, gl3);
            *(float4*)(sm + OFF_A + (so * 8 + 2 * p + 1) * SACT + ecol) =
                make_float4(gh0, gh1, gh2, gh3);
        }
        *(float4*)(sm + OFF_OUT + so * 128 + sb) = osum;
    }
    STS_RP(OFF_WB);
    __syncthreads();

    // -------- phase 5: residuals; bwd2 (A, WB)*m1 -> B; prefetch W1 -> WA (perm rows) --------
    if (tid < 128) {
        float r = bo_d;
#pragma unroll
        for (int q = 0; q < 8; ++q) r += sm[OFF_OUT + q * 128 + tid];
        out[(size_t)(tile * 128 + tid) * 8 + d] = r;
    }
    PREF_R(W1 + d * 4096);
#pragma unroll
    for (int i = 0; i < 16; ++i) acc[i] = 0ull;
    gemm8x4(sm + OFF_A, sm + OFF_WB + so * 4, 64, sb, acc);
#pragma unroll
    for (int p = 0; p < 4; ++p) {
        float2 v0 = unpk(acc[p * 4 + 0]), v1 = unpk(acc[p * 4 + 1]);
        float2 v2 = unpk(acc[p * 4 + 2]), v3 = unpk(acc[p * 4 + 3]);
        *(float4*)(sm + OFF_B + (so * 8 + 2 * p) * SACT + ecol) =
            make_float4(v0.x * mb(m1, p * 8 + 0), v1.x * mb(m1, p * 8 + 2),
                        v2.x * mb(m1, p * 8 + 4), v3.x * mb(m1, p * 8 + 6));
        *(float4*)(sm + OFF_B + (so * 8 + 2 * p + 1) * SACT + ecol) =
            make_float4(v0.y * mb(m1, p * 8 + 1), v1.y * mb(m1, p * 8 + 3),
                        v2.y * mb(m1, p * 8 + 5), v3.y * mb(m1, p * 8 + 7));
    }
    STS_RP(OFF_WA);
    __syncthreads();

    // -------- phase 6: bwd1 (B, WA)*m0 -> A; prefetch W0 raw rows -> WB --------
    float w0pre[5];
#pragma unroll
    for (int q = 0; q < 5; ++q) {
        int i = q * 256 + tid;
        w0pre[q] = (i < 1088) ? W0[d * 1088 + i] : 0.f;
    }
#pragma unroll
    for (int i = 0; i < 16; ++i) acc[i] = 0ull;
    gemm8x4(sm + OFF_B, sm + OFF_WA + so * 4, 64, sb, acc);
#pragma unroll
    for (int p = 0; p < 4; ++p) {
        float2 v0 = unpk(acc[p * 4 + 0]), v1 = unpk(acc[p * 4 + 1]);
        float2 v2 = unpk(acc[p * 4 + 2]), v3 = unpk(acc[p * 4 + 3]);
        *(float4*)(sm + OFF_A + (so * 8 + 2 * p) * SACT + ecol) =
            make_float4(v0.x * mb(m0, p * 8 + 0), v1.x * mb(m0, p * 8 + 2),
                        v2.x * mb(m0, p * 8 + 4), v3.x * mb(m0, p * 8 + 6));
        *(float4*)(sm + OFF_A + (so * 8 + 2 * p + 1) * SACT + ecol) =
            make_float4(v0.y * mb(m0, p * 8 + 1), v1.y * mb(m0, p * 8 + 3),
                        v2.y * mb(m0, p * 8 + 5), v3.y * mb(m0, p * 8 + 7));
    }
#pragma unroll
    for (int q = 0; q < 5; ++q) {
        int i = q * 256 + tid;
        if (i < 1088) {
            int h = i / 17, c = i - 17 * h;
            sm[OFF_WB + h * SW + c] = w0pre[q];    // raw layout for jac phase
        }
    }
    __syncthreads();

    // -------- phase 7: jac = g1 @ W0 (raw W0 layout; rotated act reads) --------
    {
        const int tyj = tid >> 6;      // 0..3
        const int txj = tid & 63;      // 2 samples
        if (tyj < 2) {
            u64 a2[8];
#pragma unroll
            for (int i = 0; i < 8; ++i) a2[i] = 0ull;
            const float* wp = sm + OFF_WB + tyj * 8;
#pragma unroll 4
            for (int k = 0; k < 64; ++k) {
                float2 a = *(const float2*)(sm + OFF_A + k * SACT +
                                            ((txj * 2 + ((k >> 3) << 2)) & 127));
                ulonglong2 wA = *(const ulonglong2*)(wp + k * SW);
                ulonglong2 wB = *(const ulonglong2*)(wp + k * SW + 4);
                u64 a0 = pack2(a.x, a.x), a1 = pack2(a.y, a.y);
                a2[0] = ffma2(wA.x, a0, a2[0]);  a2[1] = ffma2(wA.x, a1, a2[1]);
                a2[2] = ffma2(wA.y, a0, a2[2]);  a2[3] = ffma2(wA.y, a1, a2[3]);
                a2[4] = ffma2(wB.x, a0, a2[4]);  a2[5] = ffma2(wB.x, a1, a2[5]);
                a2[6] = ffma2(wB.y, a0, a2[6]);  a2[7] = ffma2(wB.y, a1, a2[7]);
            }
#pragma unroll
            for (int j = 0; j < 2; ++j) {
                int n = tile * 128 + txj * 2 + j;
                float2 p0 = unpk(a2[0 + j]), p1 = unpk(a2[2 + j]);
                float2 p2 = unpk(a2[4 + j]), p3 = unpk(a2[6 + j]);
                float* dst = out + 524416 + ((size_t)d * 65536 + n) * 16 + tyj * 8;
                *(float4*)dst       = make_float4(p0.x, p0.y, p1.x, p1.y);
                *(float4*)(dst + 4) = make_float4(p2.x, p2.y, p3.x, p3.y);
            }
        } else if (tyj == 2) {
            const float* wp = sm + OFF_WB + 16;
            float s0 = 0.f, s1 = 0.f;
#pragma unroll 4
            for (int k = 0; k < 64; ++k) {
                float wv = wp[k * SW];
                float2 a = *(const float2*)(sm + OFF_A + k * SACT +
                                            ((txj * 2 + ((k >> 3) << 2)) & 127));
                s0 = fmaf(wv, a.x, s0);
                s1 = fmaf(wv, a.y, s1);
            }
            sm[OFF_J + txj] = logf(fabsf(s0)) + logf(fabsf(s1));
        }
    }
    __syncthreads();

    // -------- phase 8: publish partial; last block does the logdet reduce --------
    if (tid == 0) {
        float sj = 0.f;
#pragma unroll
        for (int q = 0; q < 64; ++q) sj += sm[OFF_J + q];
        g_partials[d * 512 + tile] = sj;
        __threadfence();
        u32 v = atomicAdd(&g_done, 1u);
        sm[OFF_FLAG] = (v == 4095u) ? 1.f : 0.f;
    }
    __syncthreads();
    if (sm[OFF_FLAG] != 0.f) {
        __threadfence();   // acquire: all g_partials writes are visible
        if (tid < 128) {
            const int b = tid;
            float s = 0.f;
#pragma unroll
            for (int dd = 0; dd < 8; ++dd)
#pragma unroll
                for (int q = 0; q < 4; ++q)
                    s += g_partials[dd * 512 + b * 4 + q];
            out[524288 + b] = s;
        }
        if (tid == 0) g_done = 0;   // reset for next graph replay
    }
}

extern "C" void kernel_launch(void* const* d_in, const int* in_sizes, int n_in,
                              void* d_out, int out_size) {
    const float* x  = (const float*)d_in[0];
    const float* W0 = (const float*)d_in[1];
    const float* b0 = (const float*)d_in[2];
    const float* W1 = (const float*)d_in[3];
    const float* b1 = (const float*)d_in[4];
    const float* W2 = (const float*)d_in[5];
    const float* b2 = (const float*)d_in[6];
    const float* Wo = (const float*)d_in[7];
    const float* bo = (const float*)d_in[8];
    float* out = (float*)d_out;

    cudaFuncSetAttribute(mlp_tile_kernel,
                         cudaFuncAttributeMaxDynamicSharedMemorySize, SMEM_BYTES);
    dim3 grid(512, 8);
    mlp_tile_kernel<<<grid, 256, SMEM_BYTES>>>(x, W0, b0, W1, b1, W2, b2, Wo, bo, out);
}

// round 12
// speedup vs baseline: 1.0701x; 1.0701x over previous
#include <cuda_runtime.h>
#include <math.h>

// Fixed problem: B=128, T=514, D=8, H=64, L=2, IN=17, W=512, N=65536
// out layout: [0,524288) residuals (B,W,D) | [524288,524416) logdet (B,)
//             [524416,8913024) hist_jac (D,N,16)
#define SLOPE 0.2f
#define SACT 132          // activation row stride (128 samples + pad)
#define SW   68           // weight row stride (64 + pad)

// smem float offsets
#define OFF_OUT 0          // [8][128] partial head sums (reuses X region)
#define OFF_J   1024       // [64] logdet partials      (reuses X region)
#define OFF_X   0          // [17][SACT] layer-0 inputs (freed after layer 0)
#define OFF_A   2244       // [64][SACT] ping
#define OFF_B   10692      // [64][SACT] pong
#define OFF_WA  19140      // [64][SW] weight buffer A
#define OFF_WB  23492      // [64][SW] weight buffer B
#define OFF_SB0 27844
#define OFF_SB1 27908
#define OFF_SB2 27972
#define OFF_SWO 28036
#define OFF_FLAG 28100     // last-block flag
#define SMEM_FLOATS 28104
#define SMEM_BYTES  (SMEM_FLOATS * 4)

typedef unsigned long long u64;
typedef unsigned int u32;

__device__ float g_partials[4096];   // [d][tile] (8 x 512)
__device__ u32   g_done = 0;         // finished-block counter (reset by last block)

__device__ __forceinline__ u64 ffma2(u64 a, u64 b, u64 c) {
    u64 d; asm("fma.rn.f32x2 %0, %1, %2, %3;" : "=l"(d) : "l"(a), "l"(b), "l"(c)); return d;
}
__device__ __forceinline__ u64 pack2(float x, float y) {
    u64 r; asm("mov.b64 %0, {%1, %2};" : "=l"(r) : "f"(x), "f"(y)); return r;
}
__device__ __forceinline__ float2 unpk(u64 v) {
    float2 r; asm("mov.b64 {%0, %1}, %2;" : "=f"(r.x), "=f"(r.y) : "l"(v)); return r;
}
__device__ __forceinline__ float lk(float v) { return v > 0.f ? v : v * SLOPE; }
__device__ __forceinline__ float mb(u32 m, int b) { return ((m >> b) & 1u) ? 1.f : SLOPE; }

// Weight column permutation: h = (wy:h5)(so:h4h3)(j2:h2)(j0:h1h0)
//   perm(h) = wy*32 + j2*16 + so*4 + j0
// so that lane (wy, so) reads its 8 outs as two 16B chunks at
// wy*32 + so*4 (+0 / +16), and the warp's loads each span 64B contiguous.
// Chunk-preserving for 4-aligned h (low 2 bits pass through).
__device__ __forceinline__ int wperm(int h) {
    return ((h >> 5) << 5) + (((h >> 2) & 1) << 4) + (((h >> 3) & 3) << 2) + (h & 3);
}

// 8 outputs (4 packed pairs, outs ob..ob+7) x 4 samples per thread.
// A points at act base + sb (sample col); wp at Wc + wy*32 + so*4.
// Per k per warp: 1 act wf (multicast) + 2 weight wf.
__device__ __forceinline__ void gemm8x4(const float* __restrict__ A,
                                        const float* __restrict__ wp,
                                        int K, u64* acc) {
#pragma unroll 4
    for (int k = 0; k < K; ++k) {
        float4 a = *(const float4*)(A + k * SACT);
        ulonglong2 w01 = *(const ulonglong2*)(wp + k * SW);        // outs ob..+3
        ulonglong2 w23 = *(const ulonglong2*)(wp + k * SW + 16);   // outs ob+4..+7
        u64 a0 = pack2(a.x, a.x), a1 = pack2(a.y, a.y);
        u64 a2 = pack2(a.z, a.z), a3 = pack2(a.w, a.w);
        acc[0]  = ffma2(w01.x, a0, acc[0]);   acc[1]  = ffma2(w01.x, a1, acc[1]);
        acc[2]  = ffma2(w01.x, a2, acc[2]);   acc[3]  = ffma2(w01.x, a3, acc[3]);
        acc[4]  = ffma2(w01.y, a0, acc[4]);   acc[5]  = ffma2(w01.y, a1, acc[5]);
        acc[6]  = ffma2(w01.y, a2, acc[6]);   acc[7]  = ffma2(w01.y, a3, acc[7]);
        acc[8]  = ffma2(w23.x, a0, acc[8]);   acc[9]  = ffma2(w23.x, a1, acc[9]);
        acc[10] = ffma2(w23.x, a2, acc[10]);  acc[11] = ffma2(w23.x, a3, acc[11]);
        acc[12] = ffma2(w23.y, a0, acc[12]);  acc[13] = ffma2(w23.y, a1, acc[13]);
        acc[14] = ffma2(w23.y, a2, acc[14]);  acc[15] = ffma2(w23.y, a3, acc[15]);
    }
}

// Coalesced row-major prefetch: thread gets W[h][c4..c4+3], h=i4>>4, c4=(i4&15)*4.
#define PREF_R(SRC)                                                        \
    _Pragma("unroll")                                                      \
    for (int q = 0; q < 4; ++q) pre[q] = ((const float4*)(SRC))[q * 256 + tid];
// Backward layout: [contraction=h][perm(k)] (float4 store, chunk-preserving perm).
#define STS_RP(DST)                                                        \
    _Pragma("unroll")                                                      \
    for (int q = 0; q < 4; ++q) {                                          \
        int i4 = q * 256 + tid;                                            \
        int h = i4 >> 4, c4 = (i4 & 15) * 4;                               \
        *(float4*)(sm + (DST) + h * SW + wperm(c4)) = pre[q];              \
    }
// Forward layout: [contraction=k][perm(h)] (4 scalar stores).
#define STS_TRP(DST)                                                       \
    _Pragma("unroll")                                                      \
    for (int q = 0; q < 4; ++q) {                                          \
        int i4 = q * 256 + tid;                                            \
        int h = i4 >> 4, c4 = (i4 & 15) * 4;                               \
        float* dp = sm + (DST) + wperm(h);                                 \
        dp[(c4 + 0) * SW] = pre[q].x;                                      \
        dp[(c4 + 1) * SW] = pre[q].y;                                      \
        dp[(c4 + 2) * SW] = pre[q].z;                                      \
        dp[(c4 + 3) * SW] = pre[q].w;                                      \
    }

// Forward-activation epilogue for pair p: rows ob+2p (lo), ob+2p+1 (hi), cols sb..+3.
#define STORE_ACT(BUF, P, V0, V1, V2, V3, F)                                         \
    do {                                                                             \
        *(float4*)(sm + (BUF) + (ob + 2 * (P)) * SACT + sb) =                        \
            make_float4(F(V0.x), F(V1.x), F(V2.x), F(V3.x));                         \
        *(float4*)(sm + (BUF) + (ob + 2 * (P) + 1) * SACT + sb) =                    \
            make_float4(F(V0.y), F(V1.y), F(V2.y), F(V3.y));                         \
    } while (0)

__global__ void __launch_bounds__(256, 2)
mlp_tile_kernel(const float* __restrict__ x,
                const float* __restrict__ W0, const float* __restrict__ b0,
                const float* __restrict__ W1, const float* __restrict__ b1,
                const float* __restrict__ W2, const float* __restrict__ b2,
                const float* __restrict__ Wo, const float* __restrict__ bo,
                float* __restrict__ out)
{
    extern __shared__ float sm[];
    const int tid  = threadIdx.x;
    const int lane = tid & 31;
    const int warp = tid >> 5;      // 8 warps
    const int sx   = lane & 7;      // sample subgroup within warp (octet = one row seg)
    const int so   = lane >> 3;     // out subgroup (0..3)
    const int wy   = warp & 1;      // out half (32 outs)
    const int wx   = warp >> 1;     // sample quarter (32 samples)
    const int sb   = wx * 32 + sx * 4;          // sample base col (0..124)
    const int ob   = wy * 32 + so * 8;          // out base row (0..56)
    const int row8 = wy * 4 + so;               // OUT partial row (0..7)
    const int tile = blockIdx.x;    // 0..511 (128 samples)
    const int d    = blockIdx.y;

    const float bo_d = bo[d];

    // -------- phase 1: stage X, W0 -> WA [k][perm(h)], biases --------
    {
        const int s = tid & 127, half = tid >> 7;
        const int n = tile * 128 + s;
        const float* xb = x + (size_t)((n >> 9) * 514 + (n & 511)) * 8;
        float4 v0 = *(const float4*)(xb + half * 8);
        float4 v1 = *(const float4*)(xb + half * 8 + 4);
        float* dst = sm + OFF_X + s;
        dst[(half * 8 + 0) * SACT] = v0.x;  dst[(half * 8 + 1) * SACT] = v0.y;
        dst[(half * 8 + 2) * SACT] = v0.z;  dst[(half * 8 + 3) * SACT] = v0.w;
        dst[(half * 8 + 4) * SACT] = v1.x;  dst[(half * 8 + 5) * SACT] = v1.y;
        dst[(half * 8 + 6) * SACT] = v1.z;  dst[(half * 8 + 7) * SACT] = v1.w;
        if (half == 0) dst[16 * SACT] = xb[16 + d];
    }
    for (int i = tid; i < 1088; i += 256) {         // W0 -> [k][perm(h)]
        int h = i / 17, k = i - 17 * h;
        sm[OFF_WA + k * SW + wperm(h)] = W0[d * 1088 + i];
    }
    if (tid < 64) {
        sm[OFF_SB0 + tid] = b0[d * 64 + tid];
        sm[OFF_SB1 + tid] = b1[d * 64 + tid];
        sm[OFF_SB2 + tid] = b2[d * 64 + tid];
        sm[OFF_SWO + tid] = Wo[d * 64 + tid];
    }
    __syncthreads();

    u64 acc[16];
    u32 m0 = 0, m1 = 0;
    float4 pre[4];
    const int wcol = wy * 32 + so * 4;   // this lane's permuted weight chunk base

    // -------- phase 2: L0 (X, WA) -> A; prefetch W1 -> WB^T(perm) --------
    PREF_R(W1 + d * 4096);
#pragma unroll
    for (int p = 0; p < 4; ++p) {
        u64 bp = *(const u64*)(sm + OFF_SB0 + ob + 2 * p);
        acc[p * 4 + 0] = bp; acc[p * 4 + 1] = bp; acc[p * 4 + 2] = bp; acc[p * 4 + 3] = bp;
    }
    gemm8x4(sm + OFF_X + sb, sm + OFF_WA + wcol, 17, acc);
#pragma unroll
    for (int p = 0; p < 4; ++p) {
        float2 v0 = unpk(acc[p * 4 + 0]), v1 = unpk(acc[p * 4 + 1]);
        float2 v2 = unpk(acc[p * 4 + 2]), v3 = unpk(acc[p * 4 + 3]);
        m0 |= ((u32)(v0.x > 0.f) << (p * 8 + 0)) | ((u32)(v0.y > 0.f) << (p * 8 + 1))
            | ((u32)(v1.x > 0.f) << (p * 8 + 2)) | ((u32)(v1.y > 0.f) << (p * 8 + 3))
            | ((u32)(v2.x > 0.f) << (p * 8 + 4)) | ((u32)(v2.y > 0.f) << (p * 8 + 5))
            | ((u32)(v3.x > 0.f) << (p * 8 + 6)) | ((u32)(v3.y > 0.f) << (p * 8 + 7));
        STORE_ACT(OFF_A, p, v0, v1, v2, v3, lk);
    }
    STS_TRP(OFF_WB);
    __syncthreads();

    // -------- phase 3: L1 (A, WB) -> B; prefetch W2 -> WA^T(perm) --------
    PREF_R(W2 + d * 4096);
#pragma unroll
    for (int p = 0; p < 4; ++p) {
        u64 bp = *(const u64*)(sm + OFF_SB1 + ob + 2 * p);
        acc[p * 4 + 0] = bp; acc[p * 4 + 1] = bp; acc[p * 4 + 2] = bp; acc[p * 4 + 3] = bp;
    }
    gemm8x4(sm + OFF_A + sb, sm + OFF_WB + wcol, 64, acc);
#pragma unroll
    for (int p = 0; p < 4; ++p) {
        float2 v0 = unpk(acc[p * 4 + 0]), v1 = unpk(acc[p * 4 + 1]);
        float2 v2 = unpk(acc[p * 4 + 2]), v3 = unpk(acc[p * 4 + 3]);
        m1 |= ((u32)(v0.x > 0.f) << (p * 8 + 0)) | ((u32)(v0.y > 0.f) << (p * 8 + 1))
            | ((u32)(v1.x > 0.f) << (p * 8 + 2)) | ((u32)(v1.y > 0.f) << (p * 8 + 3))
            | ((u32)(v2.x > 0.f) << (p * 8 + 4)) | ((u32)(v2.y > 0.f) << (p * 8 + 5))
            | ((u32)(v3.x > 0.f) << (p * 8 + 6)) | ((u32)(v3.y > 0.f) << (p * 8 + 7));
        STORE_ACT(OFF_B, p, v0, v1, v2, v3, lk);
    }
    STS_TRP(OFF_WA);
    __syncthreads();

    // -------- phase 4: L2 + head (B, WA) -> g in A; prefetch W2 -> WB (perm rows) --------
    PREF_R(W2 + d * 4096);
#pragma unroll
    for (int p = 0; p < 4; ++p) {
        u64 bp = *(const u64*)(sm + OFF_SB2 + ob + 2 * p);
        acc[p * 4 + 0] = bp; acc[p * 4 + 1] = bp; acc[p * 4 + 2] = bp; acc[p * 4 + 3] = bp;
    }
    gemm8x4(sm + OFF_B + sb, sm + OFF_WA + wcol, 64, acc);
    {
        float4 osum = make_float4(0.f, 0.f, 0.f, 0.f);
#pragma unroll
        for (int p = 0; p < 4; ++p) {
            float wl = sm[OFF_SWO + ob + 2 * p];
            float wh = sm[OFF_SWO + ob + 2 * p + 1];
            float2 v0 = unpk(acc[p * 4 + 0]), v1 = unpk(acc[p * 4 + 1]);
            float2 v2 = unpk(acc[p * 4 + 2]), v3 = unpk(acc[p * 4 + 3]);
            float gl0 = wl * (v0.x > 0.f ? 1.f : SLOPE), gh0 = wh * (v0.y > 0.f ? 1.f : SLOPE);
            float gl1 = wl * (v1.x > 0.f ? 1.f : SLOPE), gh1 = wh * (v1.y > 0.f ? 1.f : SLOPE);
            float gl2 = wl * (v2.x > 0.f ? 1.f : SLOPE), gh2 = wh * (v2.y > 0.f ? 1.f : SLOPE);
            float gl3 = wl * (v3.x > 0.f ? 1.f : SLOPE), gh3 = wh * (v3.y > 0.f ? 1.f : SLOPE);
            osum.x = fmaf(gl0, v0.x, fmaf(gh0, v0.y, osum.x));
            osum.y = fmaf(gl1, v1.x, fmaf(gh1, v1.y, osum.y));
            osum.z = fmaf(gl2, v2.x, fmaf(gh2, v2.y, osum.z));
            osum.w = fmaf(gl3, v3.x, fmaf(gh3, v3.y, osum.w));
            *(float4*)(sm + OFF_A + (ob + 2 * p) * SACT + sb) =
                make_float4(gl0, gl1, gl2, gl3);
            *(float4*)(sm + OFF_A + (ob + 2 * p + 1) * SACT + sb) =
                make_float4(gh0, gh1, gh2, gh3);
        }
        *(float4*)(sm + OFF_OUT + row8 * 128 + sb) = osum;
    }
    STS_RP(OFF_WB);
    __syncthreads();

    // -------- phase 5: residuals; bwd2 (A, WB)*m1 -> B; prefetch W1 -> WA (perm rows) --------
    if (tid < 128) {
        float r = bo_d;
#pragma unroll
        for (int q = 0; q < 8; ++q) r += sm[OFF_OUT + q * 128 + tid];
        out[(size_t)(tile * 128 + tid) * 8 + d] = r;
    }
    PREF_R(W1 + d * 4096);
#pragma unroll
    for (int i = 0; i < 16; ++i) acc[i] = 0ull;
    gemm8x4(sm + OFF_A + sb, sm + OFF_WB + wcol, 64, acc);
#pragma unroll
    for (int p = 0; p < 4; ++p) {
        float2 v0 = unpk(acc[p * 4 + 0]), v1 = unpk(acc[p * 4 + 1]);
        float2 v2 = unpk(acc[p * 4 + 2]), v3 = unpk(acc[p * 4 + 3]);
        *(float4*)(sm + OFF_B + (ob + 2 * p) * SACT + sb) =
            make_float4(v0.x * mb(m1, p * 8 + 0), v1.x * mb(m1, p * 8 + 2),
                        v2.x * mb(m1, p * 8 + 4), v3.x * mb(m1, p * 8 + 6));
        *(float4*)(sm + OFF_B + (ob + 2 * p + 1) * SACT + sb) =
            make_float4(v0.y * mb(m1, p * 8 + 1), v1.y * mb(m1, p * 8 + 3),
                        v2.y * mb(m1, p * 8 + 5), v3.y * mb(m1, p * 8 + 7));
    }
    STS_RP(OFF_WA);
    __syncthreads();

    // -------- phase 6: bwd1 (B, WA)*m0 -> A; prefetch W0 raw rows -> WB --------
    float w0pre[5];
#pragma unroll
    for (int q = 0; q < 5; ++q) {
        int i = q * 256 + tid;
        w0pre[q] = (i < 1088) ? W0[d * 1088 + i] : 0.f;
    }
#pragma unroll
    for (int i = 0; i < 16; ++i) acc[i] = 0ull;
    gemm8x4(sm + OFF_B + sb, sm + OFF_WA + wcol, 64, acc);
#pragma unroll
    for (int p = 0; p < 4; ++p) {
        float2 v0 = unpk(acc[p * 4 + 0]), v1 = unpk(acc[p * 4 + 1]);
        float2 v2 = unpk(acc[p * 4 + 2]), v3 = unpk(acc[p * 4 + 3]);
        *(float4*)(sm + OFF_A + (ob + 2 * p) * SACT + sb) =
            make_float4(v0.x * mb(m0, p * 8 + 0), v1.x * mb(m0, p * 8 + 2),
                        v2.x * mb(m0, p * 8 + 4), v3.x * mb(m0, p * 8 + 6));
        *(float4*)(sm + OFF_A + (ob + 2 * p + 1) * SACT + sb) =
            make_float4(v0.y * mb(m0, p * 8 + 1), v1.y * mb(m0, p * 8 + 3),
                        v2.y * mb(m0, p * 8 + 5), v3.y * mb(m0, p * 8 + 7));
    }
#pragma unroll
    for (int q = 0; q < 5; ++q) {
        int i = q * 256 + tid;
        if (i < 1088) {
            int h = i / 17, c = i - 17 * h;
            sm[OFF_WB + h * SW + c] = w0pre[q];    // raw layout for jac phase
        }
    }
    __syncthreads();

    // -------- phase 7: jac = g1 @ W0 (raw W0 layout) --------
    {
        const int tyj = tid >> 6;      // 0..3
        const int txj = tid & 63;      // 2 samples
        if (tyj < 2) {
            u64 a2[8];
#pragma unroll
            for (int i = 0; i < 8; ++i) a2[i] = 0ull;
            const float* ap = sm + OFF_A + txj * 2;
            const float* wp = sm + OFF_WB + tyj * 8;
#pragma unroll 4
            for (int k = 0; k < 64; ++k) {
                float2 a = *(const float2*)(ap + k * SACT);
                ulonglong2 wA = *(const ulonglong2*)(wp + k * SW);
                ulonglong2 wB = *(const ulonglong2*)(wp + k * SW + 4);
                u64 a0 = pack2(a.x, a.x), a1 = pack2(a.y, a.y);
                a2[0] = ffma2(wA.x, a0, a2[0]);  a2[1] = ffma2(wA.x, a1, a2[1]);
                a2[2] = ffma2(wA.y, a0, a2[2]);  a2[3] = ffma2(wA.y, a1, a2[3]);
                a2[4] = ffma2(wB.x, a0, a2[4]);  a2[5] = ffma2(wB.x, a1, a2[5]);
                a2[6] = ffma2(wB.y, a0, a2[6]);  a2[7] = ffma2(wB.y, a1, a2[7]);
            }
#pragma unroll
            for (int j = 0; j < 2; ++j) {
                int n = tile * 128 + txj * 2 + j;
                float2 p0 = unpk(a2[0 + j]), p1 = unpk(a2[2 + j]);
                float2 p2 = unpk(a2[4 + j]), p3 = unpk(a2[6 + j]);
                float* dst = out + 524416 + ((size_t)d * 65536 + n) * 16 + tyj * 8;
                *(float4*)dst       = make_float4(p0.x, p0.y, p1.x, p1.y);
                *(float4*)(dst + 4) = make_float4(p2.x, p2.y, p3.x, p3.y);
            }
        } else if (tyj == 2) {
            const float* ap = sm + OFF_A + txj * 2;
            const float* wp = sm + OFF_WB + 16;
            float s0 = 0.f, s1 = 0.f;
#pragma unroll 4
            for (int k = 0; k < 64; ++k) {
                float wv = wp[k * SW];
                float2 a = *(const float2*)(ap + k * SACT);
                s0 = fmaf(wv, a.x, s0);
                s1 = fmaf(wv, a.y, s1);
            }
            sm[OFF_J + txj] = logf(fabsf(s0)) + logf(fabsf(s1));
        }
    }
    __syncthreads();

    // -------- phase 8: publish partial; last block does the logdet reduce --------
    if (tid == 0) {
        float sj = 0.f;
#pragma unroll
        for (int q = 0; q < 64; ++q) sj += sm[OFF_J + q];
        g_partials[d * 512 + tile] = sj;
        __threadfence();
        u32 v = atomicAdd(&g_done, 1u);
        sm[OFF_FLAG] = (v == 4095u) ? 1.f : 0.f;
    }
    __syncthreads();
    if (sm[OFF_FLAG] != 0.f) {
        __threadfence();   // acquire: all g_partials writes are visible
        if (tid < 128) {
            const int b = tid;
            float s = 0.f;
#pragma unroll
            for (int dd = 0; dd < 8; ++dd)
#pragma unroll
                for (int q = 0; q < 4; ++q)
                    s += g_partials[dd * 512 + b * 4 + q];
            out[524288 + b] = s;
        }
        if (tid == 0) g_done = 0;   // reset for next graph replay
    }
}

extern "C" void kernel_launch(void* const* d_in, const int* in_sizes, int n_in,
                              void* d_out, int out_size) {
    const float* x  = (const float*)d_in[0];
    const float* W0 = (const float*)d_in[1];
    const float* b0 = (const float*)d_in[2];
    const float* W1 = (const float*)d_in[3];
    const float* b1 = (const float*)d_in[4];
    const float* W2 = (const float*)d_in[5];
    const float* b2 = (const float*)d_in[6];
    const float* Wo = (const float*)d_in[7];
    const float* bo = (const float*)d_in[8];
    float* out = (float*)d_out;

    cudaFuncSetAttribute(mlp_tile_kernel,
                         cudaFuncAttributeMaxDynamicSharedMemorySize, SMEM_BYTES);
    dim3 grid(512, 8);
    mlp_tile_kernel<<<grid, 256, SMEM_BYTES>>>(x, W0, b0, W1, b1, W2, b2, Wo, bo, out);
}